// round 1
// baseline (speedup 1.0000x reference)
#include <cuda_runtime.h>
#include <math.h>

// ---------------------------------------------------------------------------
// Problem constants (match reference setup_inputs)
// ---------------------------------------------------------------------------
constexpr int Bc = 8;
constexpr int C  = 1024;
constexpr int Ci = 512;
constexpr int Hd = 48, Wd = 48;
constexpr int Nd = Hd * Wd;          // 2304
constexpr int Ha = 16, Wa = 16;
constexpr int Na = Ha * Wa;          // 256
constexpr int R  = 64;               // C / 16
// 1/sqrt(1 + 1e-5)
constexpr float BN_INV = 0.9999950000374997f;

// ---------------------------------------------------------------------------
// Device scratch (static — no allocation allowed)
// ---------------------------------------------------------------------------
__device__ float g_proj_det[Bc * C * Nd];   // rows 0..511 = d_x (g), 512..1023 = phi_x
__device__ float g_proj_aim[Bc * C * Na];   // rows 0..511 = a_x (g), 512..1023 = theta_x
__device__ float g_f      [Bc * Na * Nd];   // attention scores
__device__ float g_nap    [Bc * Ci * Na];   // non_aim pre-W
__device__ float g_ndp    [Bc * Ci * Nd];   // non_det pre-Q
__device__ float g_nonaim [Bc * C  * Na];   // non_aim (post W conv + bn + residual)
__device__ float g_pooled [Bc * 2  * C];    // [b][avg|max][c]

// ---------------------------------------------------------------------------
// Templated batched SGEMM: C[m,n] = alpha * sum_k opA(m,k) * opB(k,n) (+epilogue)
//   TA: A stored [K,M] (element A[k*lda+m]) else [M,K] (A[m*lda+k])
//   TB: B stored [N,K] (element B[n*ldb+k]) else [K,N] (B[k*ldb+n])
//   EPI 0: out = alpha*acc + bias[m]            (bias may be null)
//   EPI 1: out = bng[m]*BN_INV*(acc+bias[m]) + bnb[m] + resid[m*ldc+n]
// BM=BN=128, BK=8, 256 threads, 8x8 per thread. Dims must divide evenly.
// ---------------------------------------------------------------------------
constexpr int BM = 128, BN = 128, BK = 8;

template<bool TA, bool TB, int EPI>
__global__ void __launch_bounds__(256)
gemm_k(const float* __restrict__ Ag, const float* __restrict__ Bg,
       float* __restrict__ Cg,
       int M, int N, int K, int lda, int ldb, int ldc,
       long sA, long sB, long sC,
       float alpha,
       const float* __restrict__ bias,
       const float* __restrict__ bng, const float* __restrict__ bnb,
       const float* __restrict__ resid, long sR)
{
    __shared__ float As[BK][BM + 4];
    __shared__ float Bs[BK][BN + 4];

    const int bz = blockIdx.z;
    const float* A = Ag + (long)bz * sA;
    const float* B = Bg + (long)bz * sB;
    float* Cp = Cg + (long)bz * sC;
    const float* Rp = (EPI == 1) ? (resid + (long)bz * sR) : nullptr;

    const int bm = blockIdx.y * BM;
    const int bn = blockIdx.x * BN;
    const int tid = threadIdx.x;
    const int tx4 = (tid & 15) * 4;
    const int ty4 = (tid >> 4) * 4;

    // ---- global-load addressing ----
    const float* aptr; long aStep; int a_i0, a_i1;
    if constexpr (!TA) {
        int row = tid >> 1, k4 = (tid & 1) * 4;
        aptr = A + (long)(bm + row) * lda + k4;
        aStep = BK;
        a_i0 = k4; a_i1 = row;
    } else {
        int kk = tid >> 5, m4 = (tid & 31) * 4;
        aptr = A + (long)kk * lda + bm + m4;
        aStep = (long)BK * lda;
        a_i0 = kk; a_i1 = m4;
    }
    const float* bptr; long bStep; int b_i0, b_i1;
    if constexpr (!TB) {
        int kk = tid >> 5, n4 = (tid & 31) * 4;
        bptr = B + (long)kk * ldb + bn + n4;
        bStep = (long)BK * ldb;
        b_i0 = kk; b_i1 = n4;
    } else {
        int row = tid >> 1, k4 = (tid & 1) * 4;
        bptr = B + (long)(bn + row) * ldb + k4;
        bStep = BK;
        b_i0 = k4; b_i1 = row;
    }

    auto storeA = [&](float4 v) {
        if constexpr (!TA) {
            As[a_i0 + 0][a_i1] = v.x; As[a_i0 + 1][a_i1] = v.y;
            As[a_i0 + 2][a_i1] = v.z; As[a_i0 + 3][a_i1] = v.w;
        } else {
            *(float4*)&As[a_i0][a_i1] = v;
        }
    };
    auto storeB = [&](float4 v) {
        if constexpr (!TB) {
            *(float4*)&Bs[b_i0][b_i1] = v;
        } else {
            Bs[b_i0 + 0][b_i1] = v.x; Bs[b_i0 + 1][b_i1] = v.y;
            Bs[b_i0 + 2][b_i1] = v.z; Bs[b_i0 + 3][b_i1] = v.w;
        }
    };

    float acc[8][8];
    #pragma unroll
    for (int i = 0; i < 8; i++)
        #pragma unroll
        for (int j = 0; j < 8; j++) acc[i][j] = 0.f;

    // ---- prologue: tile 0 ----
    float4 ra = *(const float4*)aptr; aptr += aStep;
    float4 rb = *(const float4*)bptr; bptr += bStep;
    storeA(ra); storeB(rb);
    __syncthreads();

    const int nk = K / BK;
    for (int kt = 0; kt < nk; kt++) {
        float4 ra2, rb2;
        const bool has_next = (kt + 1 < nk);
        if (has_next) {
            ra2 = *(const float4*)aptr; aptr += aStep;
            rb2 = *(const float4*)bptr; bptr += bStep;
        }
        #pragma unroll
        for (int k = 0; k < BK; k++) {
            float4 a0 = *(const float4*)&As[k][ty4];
            float4 a1 = *(const float4*)&As[k][ty4 + 64];
            float4 b0 = *(const float4*)&Bs[k][tx4];
            float4 b1 = *(const float4*)&Bs[k][tx4 + 64];
            float ar[8] = {a0.x, a0.y, a0.z, a0.w, a1.x, a1.y, a1.z, a1.w};
            float br[8] = {b0.x, b0.y, b0.z, b0.w, b1.x, b1.y, b1.z, b1.w};
            #pragma unroll
            for (int i = 0; i < 8; i++)
                #pragma unroll
                for (int j = 0; j < 8; j++)
                    acc[i][j] += ar[i] * br[j];
        }
        __syncthreads();
        if (has_next) { storeA(ra2); storeB(rb2); }
        __syncthreads();
    }

    // ---- epilogue ----
    #pragma unroll
    for (int i = 0; i < 8; i++) {
        const int mi = bm + ((i < 4) ? (ty4 + i) : (64 + ty4 + i - 4));
        const float rbias = bias ? bias[mi] : 0.f;
        float sc = 0.f, be = 0.f;
        if constexpr (EPI == 1) { sc = bng[mi] * BN_INV; be = bnb[mi]; }
        #pragma unroll
        for (int jb = 0; jb < 2; jb++) {
            const int nj = bn + tx4 + jb * 64;
            const long off = (long)mi * ldc + nj;
            const float* a4 = &acc[i][jb * 4];
            float4 v;
            if constexpr (EPI == 0) {
                v.x = alpha * a4[0] + rbias;
                v.y = alpha * a4[1] + rbias;
                v.z = alpha * a4[2] + rbias;
                v.w = alpha * a4[3] + rbias;
            } else {
                float4 r4 = *(const float4*)&Rp[off];
                v.x = sc * (a4[0] + rbias) + be + r4.x;
                v.y = sc * (a4[1] + rbias) + be + r4.y;
                v.z = sc * (a4[2] + rbias) + be + r4.z;
                v.w = sc * (a4[3] + rbias) + be + r4.w;
            }
            *(float4*)&Cp[off] = v;
        }
    }
}

// ---------------------------------------------------------------------------
// Avg+Max pooling over spatial dim of non_aim: one warp per (b,c)
// ---------------------------------------------------------------------------
__global__ void pool_k(const float* __restrict__ na, float* __restrict__ pooled)
{
    const int gw = (int)((blockIdx.x * (long)blockDim.x + threadIdx.x) >> 5);
    const int lane = threadIdx.x & 31;
    if (gw >= Bc * C) return;
    const float* p = na + (long)gw * Na;
    float s = 0.f, m = -3.4e38f;
    #pragma unroll
    for (int i = lane; i < Na; i += 32) {
        float v = p[i]; s += v; m = fmaxf(m, v);
    }
    #pragma unroll
    for (int o = 16; o; o >>= 1) {
        s += __shfl_xor_sync(0xffffffffu, s, o);
        m = fmaxf(m, __shfl_xor_sync(0xffffffffu, m, o));
    }
    if (lane == 0) {
        const int b = gw / C, c = gw % C;
        pooled[(long)b * 2 * C + c]     = s * (1.f / Na);
        pooled[(long)b * 2 * C + C + c] = m;
    }
}

// ---------------------------------------------------------------------------
// Channel gate: shared MLP on avg & max, sigmoid. One block per batch.
//   gate = sigmoid( relu(avg W1^T + b1) W2^T + relu(max W1^T + b1) W2^T + 2 b2 )
// ---------------------------------------------------------------------------
__global__ void gate_k(const float* __restrict__ pooled,
                       const float* __restrict__ w1, const float* __restrict__ b1,
                       const float* __restrict__ w2, const float* __restrict__ b2,
                       float* __restrict__ cw)
{
    __shared__ float sv[2 * C];
    __shared__ float h[2][R];
    __shared__ float hs[R];
    const int b = blockIdx.x, tid = threadIdx.x;

    for (int i = tid; i < 2 * C; i += blockDim.x)
        sv[i] = pooled[(long)b * 2 * C + i];
    __syncthreads();

    if (tid < 2 * R) {
        const int which = tid / R, r = tid % R;
        const float* v = sv + which * C;
        const float* wr = w1 + r * C;
        float acc = b1[r];
        for (int c = 0; c < C; c++) acc += wr[c] * v[c];
        h[which][r] = fmaxf(acc, 0.f);
    }
    __syncthreads();
    if (tid < R) hs[tid] = h[0][tid] + h[1][tid];
    __syncthreads();

    for (int c = tid; c < C; c += blockDim.x) {
        const float* wc = w2 + c * R;
        float acc = 2.f * b2[c];
        #pragma unroll 8
        for (int r = 0; r < R; r++) acc += wc[r] * hs[r];
        cw[(long)b * C + c] = 1.f / (1.f + expf(-acc));
    }
}

// ---------------------------------------------------------------------------
// Elementwise channel scaling: dst = src * cw[b*C + c], float4 vectorized.
//   q_div = (spatial size)/4
// ---------------------------------------------------------------------------
__global__ void scale_k(const float* __restrict__ src, const float* __restrict__ cw,
                        float* __restrict__ dst, int q_div, long total4)
{
    const long i = blockIdx.x * (long)blockDim.x + threadIdx.x;
    if (i >= total4) return;
    const long q = i / q_div;           // = b*C + c
    const float w = cw[q];
    float4 v = ((const float4*)src)[i];
    v.x *= w; v.y *= w; v.z *= w; v.w *= w;
    ((float4*)dst)[i] = v;
}

// ---------------------------------------------------------------------------
// Launch
// ---------------------------------------------------------------------------
extern "C" void kernel_launch(void* const* d_in, const int* in_sizes, int n_in,
                              void* d_out, int out_size)
{
    (void)in_sizes; (void)n_in; (void)out_size;
    const float* detect  = (const float*)d_in[0];
    const float* aim     = (const float*)d_in[1];
    const float* g_w     = (const float*)d_in[2];
    const float* g_b     = (const float*)d_in[3];
    const float* th_w    = (const float*)d_in[4];
    const float* th_b    = (const float*)d_in[5];
    const float* ph_w    = (const float*)d_in[6];
    const float* ph_b    = (const float*)d_in[7];
    const float* W_w     = (const float*)d_in[8];
    const float* W_b     = (const float*)d_in[9];
    const float* W_bn_g  = (const float*)d_in[10];
    const float* W_bn_b  = (const float*)d_in[11];
    const float* Q_w     = (const float*)d_in[12];
    const float* Q_b     = (const float*)d_in[13];
    const float* Q_bn_g  = (const float*)d_in[14];
    const float* Q_bn_b  = (const float*)d_in[15];
    const float* m1_w    = (const float*)d_in[16];
    const float* m1_b    = (const float*)d_in[17];
    const float* m2_w    = (const float*)d_in[18];
    const float* m2_b    = (const float*)d_in[19];
    float* out = (float*)d_out;

    float *proj_det, *proj_aim, *f, *nap, *ndp, *nonaim, *pooled;
    cudaGetSymbolAddress((void**)&proj_det, g_proj_det);
    cudaGetSymbolAddress((void**)&proj_aim, g_proj_aim);
    cudaGetSymbolAddress((void**)&f,        g_f);
    cudaGetSymbolAddress((void**)&nap,      g_nap);
    cudaGetSymbolAddress((void**)&ndp,      g_ndp);
    cudaGetSymbolAddress((void**)&nonaim,   g_nonaim);
    cudaGetSymbolAddress((void**)&pooled,   g_pooled);

    const long offNonDet = 0;
    const long offActDet = (long)Bc * C * Nd;
    const long offActAim = 2 * offActDet;
    const long offCw     = offActAim + (long)Bc * C * Na;

    const int T = 256;

    // 1) d_x = g(detect)        [Ci, Nd] per batch (rows 0..511 of proj_det)
    gemm_k<false, false, 0><<<dim3(Nd / BN, Ci / BM, Bc), T>>>(
        g_w, detect, proj_det,
        Ci, Nd, C, C, Nd, Nd,
        0, (long)C * Nd, (long)C * Nd,
        1.f, g_b, nullptr, nullptr, nullptr, 0);

    // 2) phi_x = phi(detect)    (rows 512..1023 of proj_det)
    gemm_k<false, false, 0><<<dim3(Nd / BN, Ci / BM, Bc), T>>>(
        ph_w, detect, proj_det + (long)Ci * Nd,
        Ci, Nd, C, C, Nd, Nd,
        0, (long)C * Nd, (long)C * Nd,
        1.f, ph_b, nullptr, nullptr, nullptr, 0);

    // 3) a_x = g(aim)
    gemm_k<false, false, 0><<<dim3(Na / BN, Ci / BM, Bc), T>>>(
        g_w, aim, proj_aim,
        Ci, Na, C, C, Na, Na,
        0, (long)C * Na, (long)C * Na,
        1.f, g_b, nullptr, nullptr, nullptr, 0);

    // 4) theta_x = theta(aim)
    gemm_k<false, false, 0><<<dim3(Na / BN, Ci / BM, Bc), T>>>(
        th_w, aim, proj_aim + (long)Ci * Na,
        Ci, Na, C, C, Na, Na,
        0, (long)C * Na, (long)C * Na,
        1.f, th_b, nullptr, nullptr, nullptr, 0);

    // 5) f[a,d] = sum_c theta[c,a] * phi[c,d]    (TN)
    gemm_k<true, false, 0><<<dim3(Nd / BN, Na / BM, Bc), T>>>(
        proj_aim + (long)Ci * Na, proj_det + (long)Ci * Nd, f,
        Na, Nd, Ci, Na, Nd, Nd,
        (long)C * Na, (long)C * Nd, (long)Na * Nd,
        1.f, nullptr, nullptr, nullptr, nullptr, 0);

    // 6) nap[c,a] = (1/Nd) sum_d d_x[c,d] * f[a,d]   (NT)
    gemm_k<false, true, 0><<<dim3(Na / BN, Ci / BM, Bc), T>>>(
        proj_det, f, nap,
        Ci, Na, Nd, Nd, Nd, Na,
        (long)C * Nd, (long)Na * Nd, (long)Ci * Na,
        1.f / Nd, nullptr, nullptr, nullptr, nullptr, 0);

    // 7) ndp[c,d] = (1/Na) sum_a a_x[c,a] * f[a,d]   (NN)
    gemm_k<false, false, 0><<<dim3(Nd / BN, Ci / BM, Bc), T>>>(
        proj_aim, f, ndp,
        Ci, Nd, Na, Na, Nd, Nd,
        (long)C * Na, (long)Na * Nd, (long)Ci * Nd,
        1.f / Na, nullptr, nullptr, nullptr, nullptr, 0);

    // 8) non_aim = bn(W_w @ nap + W_b) + aim
    gemm_k<false, false, 1><<<dim3(Na / BN, C / BM, Bc), T>>>(
        W_w, nap, nonaim,
        C, Na, Ci, Ci, Na, Na,
        0, (long)Ci * Na, (long)C * Na,
        1.f, W_b, W_bn_g, W_bn_b, aim, (long)C * Na);

    // 9) non_det = bn(Q_w @ ndp + Q_b) + detect   -> out[0]
    gemm_k<false, false, 1><<<dim3(Nd / BN, C / BM, Bc), T>>>(
        Q_w, ndp, out + offNonDet,
        C, Nd, Ci, Ci, Nd, Nd,
        0, (long)Ci * Nd, (long)C * Nd,
        1.f, Q_b, Q_bn_g, Q_bn_b, detect, (long)C * Nd);

    // 10) pooling over non_aim
    pool_k<<<(Bc * C) / 8, 256>>>(nonaim, pooled);

    // 11) channel gate -> c_weight region of out
    gate_k<<<Bc, 256>>>(pooled, m1_w, m1_b, m2_w, m2_b, out + offCw);

    // 12) act_det = non_det * cw ; act_aim = non_aim * cw
    {
        const long t4d = (long)Bc * C * Nd / 4;
        scale_k<<<(unsigned)((t4d + 255) / 256), 256>>>(
            out + offNonDet, out + offCw, out + offActDet, Nd / 4, t4d);
        const long t4a = (long)Bc * C * Na / 4;
        scale_k<<<(unsigned)((t4a + 255) / 256), 256>>>(
            nonaim, out + offCw, out + offActAim, Na / 4, t4a);
    }
}

// round 4
// speedup vs baseline: 1.6273x; 1.6273x over previous
#include <cuda_runtime.h>
#include <cstdint>
#include <math.h>

// ---------------------------------------------------------------------------
// Problem constants
// ---------------------------------------------------------------------------
constexpr int Bc = 8;
constexpr int C  = 1024;
constexpr int Ci = 512;
constexpr int Nd = 48 * 48;          // 2304
constexpr int Na = 16 * 16;          // 256
constexpr int R  = 64;               // C / 16
constexpr float BN_INV = 0.9999950000374997f;  // 1/sqrt(1+1e-5)

// ---------------------------------------------------------------------------
// Device scratch (static)
// ---------------------------------------------------------------------------
__device__ float g_detT  [Bc * Nd * C];    // detect^T  [Nd, C]
__device__ float g_aimT  [Bc * Na * C];    // aim^T     [Na, C]
__device__ float g_dx    [Bc * Ci * Nd];   // d_x   [Ci, Nd]
__device__ float g_phx   [Bc * Nd * Ci];   // phi_x [Nd, Ci]
__device__ float g_ax    [Bc * Ci * Na];   // a_x   [Ci, Na]
__device__ float g_thx   [Bc * Na * Ci];   // theta [Na, Ci]
__device__ float g_fm    [Bc * Na * Nd];   // f     [Na, Nd]
__device__ float g_fT    [Bc * Nd * Na];   // f^T   [Nd, Na]
__device__ float g_nap   [Bc * Na * Ci];   // nap   [Na, Ci]
__device__ float g_ndp   [Bc * Nd * Ci];   // ndp   [Nd, Ci]
__device__ float g_nonaim[Bc * C  * Na];   // non_aim [C, Na]
__device__ float g_pooled[Bc * 2  * C];

// ---------------------------------------------------------------------------
// tf32 helpers
// ---------------------------------------------------------------------------
__device__ __forceinline__ uint32_t f2tf(float x) {
    uint32_t r;
    asm("cvt.rna.tf32.f32 %0, %1;" : "=r"(r) : "f"(x));
    return r;
}
__device__ __forceinline__ void mma8(float* d, const uint32_t* a, const uint32_t* b) {
    asm volatile(
        "mma.sync.aligned.m16n8k8.row.col.f32.tf32.tf32.f32 "
        "{%0,%1,%2,%3}, {%4,%5,%6,%7}, {%8,%9}, {%0,%1,%2,%3};"
        : "+f"(d[0]), "+f"(d[1]), "+f"(d[2]), "+f"(d[3])
        : "r"(a[0]), "r"(a[1]), "r"(a[2]), "r"(a[3]), "r"(b[0]), "r"(b[1]));
}

// ---------------------------------------------------------------------------
// tf32 mma.sync GEMM:  D[M,N] = alpha * A[M,K] * B[N,K]^T  (+ epilogue)
//   Block 128x128, BK=16 double-buffered, 8 warps (4m x 2n), warp tile 32x64.
//   Smem stride 20 words -> conflict-free fragment loads (20*g mod 32 spans
//   all 32 banks over g=0..7). Requires M%128==0, N%128==0, K%16==0,
//   row stride == K.
//   EPI 0: alpha*acc (+ bM[m] if BMODE==1, + bN[n] if BMODE==2)
//   EPI 1: bng[m]*BN_INV*(acc+bM[m]) + bnb[m] + resid[m*ldc+n]
//   EPI 2: EPI1 value v; additionally out2 = v * cw[bz*M + m]
// ---------------------------------------------------------------------------
constexpr int SA   = 20;          // padded k-stride in words (16 + 4)
constexpr int TILE = 128 * SA;    // words per operand per stage

template<int EPI, int BMODE>
__global__ void __launch_bounds__(256)
tgemm(const float* __restrict__ A, const float* __restrict__ B,
      float* __restrict__ Co,
      int K, int ldc, long strA, long strB, long strC, float alpha,
      const float* __restrict__ bM, const float* __restrict__ bN,
      const float* __restrict__ bng, const float* __restrict__ bnb,
      const float* __restrict__ resid, long sR,
      const float* __restrict__ cw, float* __restrict__ out2)
{
    __shared__ uint32_t As[2 * TILE];
    __shared__ uint32_t Bs[2 * TILE];

    const int tid = threadIdx.x, lane = tid & 31, wid = tid >> 5;
    const int wm = wid & 3, wn = wid >> 2;           // warp grid 4(m) x 2(n)
    const int bz = blockIdx.z;
    const int bm = blockIdx.y * 128, bn = blockIdx.x * 128;

    // loader addressing: thread t -> row t/2, k-offset (t&1)*8 (8 floats each)
    const int lr = tid >> 1, lk = (tid & 1) * 8;
    const float* apg = A + (long)bz * strA + (long)(bm + lr) * K + lk;
    const float* bpg = B + (long)bz * strB + (long)(bn + lr) * K + lk;

    float acc[2][8][4];
    #pragma unroll
    for (int i = 0; i < 2; i++)
        #pragma unroll
        for (int j = 0; j < 8; j++)
            #pragma unroll
            for (int q = 0; q < 4; q++) acc[i][j][q] = 0.f;

    float4 ra0, ra1, rb0, rb1;
    auto g2r = [&](int kt) {
        const float* ap = apg + kt * 16;
        const float* bp = bpg + kt * 16;
        ra0 = *(const float4*)ap;       ra1 = *(const float4*)(ap + 4);
        rb0 = *(const float4*)bp;       rb1 = *(const float4*)(bp + 4);
    };
    auto r2s = [&](int st) {
        uint32_t* as = As + st * TILE + lr * SA + lk;
        uint32_t* bs = Bs + st * TILE + lr * SA + lk;
        *(uint4*)(as + 0) = make_uint4(f2tf(ra0.x), f2tf(ra0.y), f2tf(ra0.z), f2tf(ra0.w));
        *(uint4*)(as + 4) = make_uint4(f2tf(ra1.x), f2tf(ra1.y), f2tf(ra1.z), f2tf(ra1.w));
        *(uint4*)(bs + 0) = make_uint4(f2tf(rb0.x), f2tf(rb0.y), f2tf(rb0.z), f2tf(rb0.w));
        *(uint4*)(bs + 4) = make_uint4(f2tf(rb1.x), f2tf(rb1.y), f2tf(rb1.z), f2tf(rb1.w));
    };
    auto compute = [&](int st) {
        const uint32_t* asb = As + st * TILE;
        const uint32_t* bsb = Bs + st * TILE;
        const int g = lane >> 2, t = lane & 3;
        #pragma unroll
        for (int k8 = 0; k8 < 2; k8++) {
            const int kb = k8 * 8;
            uint32_t af[2][4];
            #pragma unroll
            for (int mi = 0; mi < 2; mi++) {
                const uint32_t* p = asb + (wm * 32 + mi * 16 + g) * SA + kb + t;
                af[mi][0] = p[0];
                af[mi][1] = p[8 * SA];
                af[mi][2] = p[4];
                af[mi][3] = p[8 * SA + 4];
            }
            #pragma unroll
            for (int ni = 0; ni < 8; ni++) {
                const uint32_t* p = bsb + (wn * 64 + ni * 8 + g) * SA + kb + t;
                uint32_t bf[2] = { p[0], p[4] };
                mma8(acc[0][ni], af[0], bf);
                mma8(acc[1][ni], af[1], bf);
            }
        }
    };

    const int nk = K / 16;
    g2r(0); r2s(0);
    __syncthreads();
    for (int kt = 0; kt < nk; kt++) {
        const int s = kt & 1;
        if (kt + 1 < nk) g2r(kt + 1);      // global latency overlapped
        compute(s);
        if (kt + 1 < nk) r2s(s ^ 1);       // stage s^1 drained at end of kt-1
        __syncthreads();
    }

    // ---- epilogue ----
    const int g = lane >> 2, t2 = (lane & 3) * 2;
    #pragma unroll
    for (int mi = 0; mi < 2; mi++) {
        #pragma unroll
        for (int half = 0; half < 2; half++) {
            const int m = bm + wm * 32 + mi * 16 + half * 8 + g;
            float addM = 0.f, sc = 1.f, be = 0.f, gwv = 0.f;
            if constexpr (EPI == 0) {
                if constexpr (BMODE == 1) addM = bM[m];
            } else {
                addM = bM[m]; sc = bng[m] * BN_INV; be = bnb[m];
            }
            float* crow = Co + (long)bz * strC + (long)m * ldc;
            const float* rrow = nullptr;
            float* o2row = nullptr;
            if constexpr (EPI >= 1) rrow = resid + (long)bz * sR + (long)m * ldc;
            if constexpr (EPI == 2) {
                o2row = out2 + (long)bz * strC + (long)m * ldc;
                gwv = cw[(long)bz * (gridDim.y * 128) + m];
            }
            #pragma unroll
            for (int ni = 0; ni < 8; ni++) {
                const int n = bn + wn * 64 + ni * 8 + t2;
                const float c0 = acc[mi][ni][half * 2 + 0];
                const float c1 = acc[mi][ni][half * 2 + 1];
                float2 o;
                if constexpr (EPI == 0) {
                    o.x = alpha * c0 + addM;
                    o.y = alpha * c1 + addM;
                    if constexpr (BMODE == 2) { o.x += bN[n]; o.y += bN[n + 1]; }
                } else {
                    float2 rv = *(const float2*)&rrow[n];
                    o.x = sc * (c0 + addM) + be + rv.x;
                    o.y = sc * (c1 + addM) + be + rv.y;
                }
                *(float2*)&crow[n] = o;
                if constexpr (EPI == 2) {
                    float2 o2 = { o.x * gwv, o.y * gwv };
                    *(float2*)&o2row[n] = o2;
                }
            }
        }
    }
}

// ---------------------------------------------------------------------------
// Transpose: src [rows][cols] -> dst [cols][rows], per batch z
// ---------------------------------------------------------------------------
__global__ void transpose_k(const float* __restrict__ src, float* __restrict__ dst,
                            int rows, int cols)
{
    __shared__ float t[32][33];
    const long bo = (long)blockIdx.z * rows * cols;
    const int c0 = blockIdx.x * 32, r0 = blockIdx.y * 32;
    const int tx = threadIdx.x, ty = threadIdx.y;
    #pragma unroll
    for (int i = 0; i < 32; i += 8)
        t[ty + i][tx] = src[bo + (long)(r0 + ty + i) * cols + c0 + tx];
    __syncthreads();
    #pragma unroll
    for (int i = 0; i < 32; i += 8)
        dst[bo + (long)(c0 + ty + i) * rows + r0 + tx] = t[tx][ty + i];
}

// ---------------------------------------------------------------------------
// Avg+Max pooling over non_aim spatial dim: one warp per (b,c)
// ---------------------------------------------------------------------------
__global__ void pool_k(const float* __restrict__ na, float* __restrict__ pooled)
{
    const int gw = (int)((blockIdx.x * (long)blockDim.x + threadIdx.x) >> 5);
    const int lane = threadIdx.x & 31;
    if (gw >= Bc * C) return;
    const float* p = na + (long)gw * Na;
    float s = 0.f, m = -3.4e38f;
    for (int i = lane; i < Na; i += 32) { float v = p[i]; s += v; m = fmaxf(m, v); }
    #pragma unroll
    for (int o = 16; o; o >>= 1) {
        s += __shfl_xor_sync(0xffffffffu, s, o);
        m = fmaxf(m, __shfl_xor_sync(0xffffffffu, m, o));
    }
    if (lane == 0) {
        const int b = gw / C, c = gw % C;
        pooled[(long)b * 2 * C + c]     = s * (1.f / Na);
        pooled[(long)b * 2 * C + C + c] = m;
    }
}

// ---------------------------------------------------------------------------
// Channel gate MLP + sigmoid, one block per batch
// ---------------------------------------------------------------------------
__global__ void gate_k(const float* __restrict__ pooled,
                       const float* __restrict__ w1, const float* __restrict__ b1,
                       const float* __restrict__ w2, const float* __restrict__ b2,
                       float* __restrict__ cw)
{
    __shared__ float sv[2 * C];
    __shared__ float h[2][R];
    __shared__ float hs[R];
    const int b = blockIdx.x, tid = threadIdx.x;
    for (int i = tid; i < 2 * C; i += blockDim.x)
        sv[i] = pooled[(long)b * 2 * C + i];
    __syncthreads();
    if (tid < 2 * R) {
        const int which = tid / R, r = tid % R;
        const float* v = sv + which * C;
        const float* wr = w1 + r * C;
        float acc = b1[r];
        for (int c = 0; c < C; c++) acc += wr[c] * v[c];
        h[which][r] = fmaxf(acc, 0.f);
    }
    __syncthreads();
    if (tid < R) hs[tid] = h[0][tid] + h[1][tid];
    __syncthreads();
    for (int c = tid; c < C; c += blockDim.x) {
        const float* wc = w2 + c * R;
        float acc = 2.f * b2[c];
        #pragma unroll 8
        for (int r = 0; r < R; r++) acc += wc[r] * hs[r];
        cw[(long)b * C + c] = 1.f / (1.f + expf(-acc));
    }
}

// ---------------------------------------------------------------------------
// Channel scaling (act_aim): dst = src * cw[b*C + c]
// ---------------------------------------------------------------------------
__global__ void scale_k(const float* __restrict__ src, const float* __restrict__ cw,
                        float* __restrict__ dst, int q_div, long total4)
{
    const long i = blockIdx.x * (long)blockDim.x + threadIdx.x;
    if (i >= total4) return;
    const float w = cw[i / q_div];
    float4 v = ((const float4*)src)[i];
    v.x *= w; v.y *= w; v.z *= w; v.w *= w;
    ((float4*)dst)[i] = v;
}

// ---------------------------------------------------------------------------
// Launch
// ---------------------------------------------------------------------------
extern "C" void kernel_launch(void* const* d_in, const int* in_sizes, int n_in,
                              void* d_out, int out_size)
{
    (void)in_sizes; (void)n_in; (void)out_size;
    const float* detect = (const float*)d_in[0];
    const float* aim    = (const float*)d_in[1];
    const float* g_w    = (const float*)d_in[2];
    const float* g_b    = (const float*)d_in[3];
    const float* th_w   = (const float*)d_in[4];
    const float* th_b   = (const float*)d_in[5];
    const float* ph_w   = (const float*)d_in[6];
    const float* ph_b   = (const float*)d_in[7];
    const float* W_w    = (const float*)d_in[8];
    const float* W_b    = (const float*)d_in[9];
    const float* W_bn_g = (const float*)d_in[10];
    const float* W_bn_b = (const float*)d_in[11];
    const float* Q_w    = (const float*)d_in[12];
    const float* Q_b    = (const float*)d_in[13];
    const float* Q_bn_g = (const float*)d_in[14];
    const float* Q_bn_b = (const float*)d_in[15];
    const float* m1_w   = (const float*)d_in[16];
    const float* m1_b   = (const float*)d_in[17];
    const float* m2_w   = (const float*)d_in[18];
    const float* m2_b   = (const float*)d_in[19];
    float* out = (float*)d_out;

    float *detT, *aimT, *dx, *phx, *ax, *thx, *fm, *fT, *nap, *ndp, *nonaim, *pooled;
    cudaGetSymbolAddress((void**)&detT,   g_detT);
    cudaGetSymbolAddress((void**)&aimT,   g_aimT);
    cudaGetSymbolAddress((void**)&dx,     g_dx);
    cudaGetSymbolAddress((void**)&phx,    g_phx);
    cudaGetSymbolAddress((void**)&ax,     g_ax);
    cudaGetSymbolAddress((void**)&thx,    g_thx);
    cudaGetSymbolAddress((void**)&fm,     g_fm);
    cudaGetSymbolAddress((void**)&fT,     g_fT);
    cudaGetSymbolAddress((void**)&nap,    g_nap);
    cudaGetSymbolAddress((void**)&ndp,    g_ndp);
    cudaGetSymbolAddress((void**)&nonaim, g_nonaim);
    cudaGetSymbolAddress((void**)&pooled, g_pooled);

    const long offNonDet = 0;
    const long offActDet = (long)Bc * C * Nd;
    const long offActAim = 2 * offActDet;
    const long offCw     = offActAim + (long)Bc * C * Na;

    // T0: transposes (detect/aim are [C, N]; GEMMs want K=C contiguous rows)
    transpose_k<<<dim3(Nd / 32, C / 32, Bc), dim3(32, 8)>>>(detect, detT, C, Nd);
    transpose_k<<<dim3(Na / 32, C / 32, Bc), dim3(32, 8)>>>(aim,    aimT, C, Na);

    // G1: d_x[Ci,Nd] = g_w * detT^T + g_b[m]
    tgemm<0,1><<<dim3(Nd/128, Ci/128, Bc), 256>>>(
        g_w, detT, dx, C, Nd, 0, (long)Nd*C, (long)Ci*Nd, 1.f,
        g_b, nullptr, nullptr, nullptr, nullptr, 0, nullptr, nullptr);
    // G2: phi_x[Nd,Ci] = detT * ph_w^T + ph_b[n]
    tgemm<0,2><<<dim3(Ci/128, Nd/128, Bc), 256>>>(
        detT, ph_w, phx, C, Ci, (long)Nd*C, 0, (long)Nd*Ci, 1.f,
        nullptr, ph_b, nullptr, nullptr, nullptr, 0, nullptr, nullptr);
    // G3: a_x[Ci,Na] = g_w * aimT^T + g_b[m]
    tgemm<0,1><<<dim3(Na/128, Ci/128, Bc), 256>>>(
        g_w, aimT, ax, C, Na, 0, (long)Na*C, (long)Ci*Na, 1.f,
        g_b, nullptr, nullptr, nullptr, nullptr, 0, nullptr, nullptr);
    // G4: theta_x[Na,Ci] = aimT * th_w^T + th_b[n]
    tgemm<0,2><<<dim3(Ci/128, Na/128, Bc), 256>>>(
        aimT, th_w, thx, C, Ci, (long)Na*C, 0, (long)Na*Ci, 1.f,
        nullptr, th_b, nullptr, nullptr, nullptr, 0, nullptr, nullptr);
    // G5: f[Na,Nd] = theta * phi^T
    tgemm<0,0><<<dim3(Nd/128, Na/128, Bc), 256>>>(
        thx, phx, fm, Ci, Nd, (long)Na*Ci, (long)Nd*Ci, (long)Na*Nd, 1.f,
        nullptr, nullptr, nullptr, nullptr, nullptr, 0, nullptr, nullptr);
    // G5b: fT[Nd,Na] = phi * theta^T
    tgemm<0,0><<<dim3(Na/128, Nd/128, Bc), 256>>>(
        phx, thx, fT, Ci, Na, (long)Nd*Ci, (long)Na*Ci, (long)Nd*Na, 1.f,
        nullptr, nullptr, nullptr, nullptr, nullptr, 0, nullptr, nullptr);
    // G6: nap[Na,Ci] = (1/Nd) f * d_x^T
    tgemm<0,0><<<dim3(Ci/128, Na/128, Bc), 256>>>(
        fm, dx, nap, Nd, Ci, (long)Na*Nd, (long)Ci*Nd, (long)Na*Ci, 1.f/Nd,
        nullptr, nullptr, nullptr, nullptr, nullptr, 0, nullptr, nullptr);
    // G7: ndp[Nd,Ci] = (1/Na) fT * a_x^T
    tgemm<0,0><<<dim3(Ci/128, Nd/128, Bc), 256>>>(
        fT, ax, ndp, Na, Ci, (long)Nd*Na, (long)Ci*Na, (long)Nd*Ci, 1.f/Na,
        nullptr, nullptr, nullptr, nullptr, nullptr, 0, nullptr, nullptr);
    // G8: non_aim[C,Na] = bn(W_w * nap^T + W_b) + aim
    tgemm<1,0><<<dim3(Na/128, C/128, Bc), 256>>>(
        W_w, nap, nonaim, Ci, Na, 0, (long)Na*Ci, (long)C*Na, 1.f,
        W_b, nullptr, W_bn_g, W_bn_b, aim, (long)C*Na, nullptr, nullptr);
    // pool + gate
    pool_k<<<(Bc * C) / 8, 256>>>(nonaim, pooled);
    gate_k<<<Bc, 256>>>(pooled, m1_w, m1_b, m2_w, m2_b, out + offCw);
    // G9: non_det[C,Nd] = bn(Q_w * ndp^T + Q_b) + detect ; act_det fused
    tgemm<2,0><<<dim3(Nd/128, C/128, Bc), 256>>>(
        Q_w, ndp, out + offNonDet, Ci, Nd, 0, (long)Nd*Ci, (long)C*Nd, 1.f,
        Q_b, nullptr, Q_bn_g, Q_bn_b, detect, (long)C*Nd,
        out + offCw, out + offActDet);
    // act_aim = non_aim * cw
    const long t4a = (long)Bc * C * Na / 4;
    scale_k<<<(unsigned)((t4a + 255) / 256), 256>>>(
        nonaim, out + offCw, out + offActAim, Na / 4, t4a);
}